// round 9
// baseline (speedup 1.0000x reference)
#include <cuda_runtime.h>
#include <cuda_fp16.h>
#include <cuda_bf16.h>
#include <mma.h>

using namespace nvcuda;

// ---------------------------------------------------------------------------
// PhysicsConvolution: X0 = notes@w ; X1 = segment_sum(ew * X0[dst], src) ;
// out = concat(relu(X1 + b), X0[garment:])
//
// R9 = R8 (145.2us) + ONE change: GEMM warp tile 16x64 -> 32x64 with
// BM=128 block tile (0.5 smem loads/MMA instead of 0.83; half the blocks,
// half the W staging).
// ---------------------------------------------------------------------------

#define HD   128
#define BM   128
#define PAD  136

#define MAXN 131072
#define MAXE 1700000
#define SCAN_BLK 1024

#define SMEM_BYTES ((2 * HD * PAD + 2 * BM * PAD) * 2)   // 136 KB

__device__ uint2  g_X0h[3400000];       // fp16 X0: [N][32] x 4 halves
__device__ int2   g_sdw[MAXE];          // CSR payload {dst, w}
__device__ int    g_cnt[MAXN + 1];      // zero at load; scan restores zeros
__device__ int    g_off[MAXN + 2];
__device__ int    g_cur[MAXN + 1];
__device__ unsigned long long g_agg[256]; // lookback flags; scatter resets

// ---------------------------------------------------------------------------
// GEMM via split-fp16 HMMA; W split fp32->hi/lo in smem per block.
// Block: 256 thr = 8 warps; tile 128 rows x 128 cols.
// Warp (wr = wid/2, wc = wid%2): rows wr*32..+31, cols wc*64..+63.
// ---------------------------------------------------------------------------
__global__ __launch_bounds__(256) void gemm_kernel(
    const float4* __restrict__ A4,
    const float4* __restrict__ W4,
    float4* __restrict__ out4,
    int N, int g)
{
    extern __shared__ char smem[];
    __half* sWh = reinterpret_cast<__half*>(smem);        // HD x PAD
    __half* sWl = sWh + HD * PAD;                         // HD x PAD
    __half* sAh = sWl + HD * PAD;                         // BM x PAD
    __half* sAl = sAh + BM * PAD;                         // BM x PAD
    float*  sC  = reinterpret_cast<float*>(sAh);          // BM x HD (aliases A)

    const int tid  = threadIdx.x;
    const int row0 = blockIdx.x * BM;

    // Stage W: fp32 -> (hi, lo) fp16 split in smem.
    #pragma unroll
    for (int i = tid; i < HD * 32; i += 256) {
        int row = i >> 5, c4 = (i & 31) * 4;
        float4 wv = W4[i];
        __half hv[4], lv[4];
        #pragma unroll
        for (int u = 0; u < 4; u++) {
            float  v  = (&wv.x)[u];
            __half hi = __float2half_rn(v);
            hv[u] = hi;
            lv[u] = __float2half_rn(v - __half2float(hi));
        }
        *reinterpret_cast<uint2*>(sWh + row * PAD + c4) =
            *reinterpret_cast<uint2*>(hv);
        *reinterpret_cast<uint2*>(sWl + row * PAD + c4) =
            *reinterpret_cast<uint2*>(lv);
    }

    // Stage A tile: fp32 -> (hi, lo) fp16 split in smem.
    #pragma unroll
    for (int i = tid; i < BM * 32; i += 256) {
        int rl = i >> 5, c4 = (i & 31) * 4;
        int r  = row0 + rl;
        float4 a = (r < N) ? A4[(size_t)r * 32 + (i & 31)]
                           : make_float4(0.f, 0.f, 0.f, 0.f);
        __half hv[4], lv[4];
        #pragma unroll
        for (int u = 0; u < 4; u++) {
            float  v  = (&a.x)[u];
            __half hi = __float2half_rn(v);
            hv[u] = hi;
            lv[u] = __float2half_rn(v - __half2float(hi));
        }
        *reinterpret_cast<uint2*>(sAh + rl * PAD + c4) =
            *reinterpret_cast<uint2*>(hv);
        *reinterpret_cast<uint2*>(sAl + rl * PAD + c4) =
            *reinterpret_cast<uint2*>(lv);
    }
    __syncthreads();

    const int wid = tid >> 5;
    const int wr  = wid >> 1;          // 0..3: rows wr*32..+31
    const int wc  = wid & 1;           // 0..1: cols wc*64..+63

    wmma::fragment<wmma::accumulator, 16, 16, 16, float> acc[2][4];
    #pragma unroll
    for (int r = 0; r < 2; r++)
        #pragma unroll
        for (int j = 0; j < 4; j++) wmma::fill_fragment(acc[r][j], 0.f);

    #pragma unroll
    for (int k = 0; k < 8; k++) {
        const int k0 = k * 16;
        wmma::fragment<wmma::matrix_a, 16, 16, 16, __half, wmma::row_major> ah[2], al[2];
        #pragma unroll
        for (int r = 0; r < 2; r++) {
            const int rowb = (wr * 32 + r * 16) * PAD + k0;
            wmma::load_matrix_sync(ah[r], sAh + rowb, PAD);
            wmma::load_matrix_sync(al[r], sAl + rowb, PAD);
        }
        #pragma unroll
        for (int j = 0; j < 4; j++) {
            const int col = wc * 64 + j * 16;
            wmma::fragment<wmma::matrix_b, 16, 16, 16, __half, wmma::row_major> bh, bl;
            wmma::load_matrix_sync(bh, sWh + k0 * PAD + col, PAD);
            wmma::load_matrix_sync(bl, sWl + k0 * PAD + col, PAD);
            #pragma unroll
            for (int r = 0; r < 2; r++) {
                wmma::mma_sync(acc[r][j], ah[r], bh, acc[r][j]);
                wmma::mma_sync(acc[r][j], ah[r], bl, acc[r][j]);
                wmma::mma_sync(acc[r][j], al[r], bh, acc[r][j]);
            }
        }
    }

    __syncthreads();   // done reading A region; reuse as fp32 C
    #pragma unroll
    for (int r = 0; r < 2; r++)
        #pragma unroll
        for (int j = 0; j < 4; j++)
            wmma::store_matrix_sync(
                sC + (wr * 32 + r * 16) * HD + wc * 64 + j * 16,
                acc[r][j], HD, wmma::mem_row_major);
    __syncthreads();

    // Pack: fp16 X0 for gather, fp32 tail rows for out.
    const int tx = tid & 31;
    const int ty = tid >> 5;
    #pragma unroll
    for (int i = 0; i < 16; i++) {
        int rl = ty * 16 + i;
        int r  = row0 + rl;
        if (r < N) {
            float4 v = *reinterpret_cast<float4*>(sC + rl * HD + tx * 4);
            __half2 lo = __float22half2_rn(make_float2(v.x, v.y));
            __half2 hi = __float22half2_rn(make_float2(v.z, v.w));
            uint2 p;
            p.x = *reinterpret_cast<unsigned*>(&lo);
            p.y = *reinterpret_cast<unsigned*>(&hi);
            g_X0h[(size_t)r * 32 + tx] = p;
            if (r >= g)
                out4[(size_t)(N + r - g) * 32 + tx] = v;
        }
    }
}

// ---------------------------------------------------------------------------
// Histogram of edge sources.
// ---------------------------------------------------------------------------
__global__ void hist_kernel(const int* __restrict__ esrc, int E) {
    for (int e = blockIdx.x * blockDim.x + threadIdx.x; e < E;
         e += gridDim.x * blockDim.x)
        atomicAdd(&g_cnt[esrc[e]], 1);
}

// ---------------------------------------------------------------------------
// Fused exclusive scan (decoupled lookback), identical to R8.
// ---------------------------------------------------------------------------
__global__ __launch_bounds__(256) void scan_kernel(int N, int E) {
    __shared__ int ssum[256];
    __shared__ int s_bpre;
    const int t   = threadIdx.x;
    const int bid = blockIdx.x;
    const int base = bid * SCAN_BLK + t * 4;

    int c0 = 0, c1 = 0, c2 = 0, c3 = 0;
    if (base + 0 < N) { c0 = g_cnt[base + 0]; g_cnt[base + 0] = 0; }
    if (base + 1 < N) { c1 = g_cnt[base + 1]; g_cnt[base + 1] = 0; }
    if (base + 2 < N) { c2 = g_cnt[base + 2]; g_cnt[base + 2] = 0; }
    if (base + 3 < N) { c3 = g_cnt[base + 3]; g_cnt[base + 3] = 0; }
    int tot = c0 + c1 + c2 + c3;

    ssum[t] = tot;
    __syncthreads();
    #pragma unroll
    for (int off = 1; off < 256; off <<= 1) {
        int v = (t >= off) ? ssum[t - off] : 0;
        __syncthreads();
        ssum[t] += v;
        __syncthreads();
    }
    int ex = ssum[t] - tot;

    if (t == 0)
        atomicExch(&g_agg[bid], (1ULL << 32) | (unsigned)ssum[255]);

    if (t < 32) {
        int prefix = 0;
        for (int ws = 0; ws < bid; ws += 32) {
            int j = ws + t;
            unsigned val = 0;
            if (j < bid) {
                unsigned long long v;
                do { v = atomicAdd(&g_agg[j], 0ULL); } while (!(v >> 32));
                val = (unsigned)v;
            }
            #pragma unroll
            for (int o = 16; o; o >>= 1)
                val += __shfl_down_sync(0xffffffffu, val, o);
            if (t == 0) prefix += (int)val;
        }
        if (t == 0) s_bpre = prefix;
    }
    __syncthreads();

    const int boff = s_bpre;
    if (base + 0 < N) { int v = ex + boff;                g_off[base + 0] = v; g_cur[base + 0] = v; }
    if (base + 1 < N) { int v = ex + c0 + boff;           g_off[base + 1] = v; g_cur[base + 1] = v; }
    if (base + 2 < N) { int v = ex + c0 + c1 + boff;      g_off[base + 2] = v; g_cur[base + 2] = v; }
    if (base + 3 < N) { int v = ex + c0 + c1 + c2 + boff; g_off[base + 3] = v; g_cur[base + 3] = v; }
    if (bid == 0 && t == 0) g_off[N] = E;
}

// ---------------------------------------------------------------------------
// Scatter edges into CSR order; also resets g_agg for the next call.
// ---------------------------------------------------------------------------
__global__ void scatter_kernel(const int* __restrict__ esrc,
                               const int* __restrict__ edst,
                               const float* __restrict__ ew, int E) {
    if (blockIdx.x == 0 && threadIdx.x < 256)
        g_agg[threadIdx.x] = 0ULL;
    for (int e = blockIdx.x * blockDim.x + threadIdx.x; e < E;
         e += gridDim.x * blockDim.x) {
        int s = esrc[e];
        int p = atomicAdd(&g_cur[s], 1);
        g_sdw[p] = make_int2(edst[e], __float_as_int(ew[e]));
    }
}

// ---------------------------------------------------------------------------
// Gather (identical to R8)
// ---------------------------------------------------------------------------
__global__ __launch_bounds__(256) void gather_kernel(
    const float4* __restrict__ b4,
    float4* __restrict__ out4,
    int N)
{
    const int lane = threadIdx.x & 31;
    const int node = (blockIdx.x * blockDim.x + threadIdx.x) >> 5;
    if (node >= N) return;

    const int start = g_off[node];
    const int end   = g_off[node + 1];

    float4 acc = make_float4(0.f, 0.f, 0.f, 0.f);

    for (int j = start; j < end; j += 32) {
        const int m = min(32, end - j);
        int   dv = 0;
        float wv = 0.f;
        if (lane < m) {
            int2 p = g_sdw[j + lane];
            dv = p.x;
            wv = __int_as_float(p.y);
        }
        int k = 0;
        for (; k + 4 <= m; k += 4) {
            int   d0 = __shfl_sync(0xffffffffu, dv, k + 0);
            int   d1 = __shfl_sync(0xffffffffu, dv, k + 1);
            int   d2 = __shfl_sync(0xffffffffu, dv, k + 2);
            int   d3 = __shfl_sync(0xffffffffu, dv, k + 3);
            float w0 = __shfl_sync(0xffffffffu, wv, k + 0);
            float w1 = __shfl_sync(0xffffffffu, wv, k + 1);
            float w2 = __shfl_sync(0xffffffffu, wv, k + 2);
            float w3 = __shfl_sync(0xffffffffu, wv, k + 3);
            uint2 u0 = g_X0h[(size_t)d0 * 32 + lane];
            uint2 u1 = g_X0h[(size_t)d1 * 32 + lane];
            uint2 u2 = g_X0h[(size_t)d2 * 32 + lane];
            uint2 u3 = g_X0h[(size_t)d3 * 32 + lane];
            float2 a0 = __half22float2(*reinterpret_cast<__half2*>(&u0.x));
            float2 b0 = __half22float2(*reinterpret_cast<__half2*>(&u0.y));
            float2 a1 = __half22float2(*reinterpret_cast<__half2*>(&u1.x));
            float2 b1 = __half22float2(*reinterpret_cast<__half2*>(&u1.y));
            float2 a2 = __half22float2(*reinterpret_cast<__half2*>(&u2.x));
            float2 b2 = __half22float2(*reinterpret_cast<__half2*>(&u2.y));
            float2 a3 = __half22float2(*reinterpret_cast<__half2*>(&u3.x));
            float2 b3 = __half22float2(*reinterpret_cast<__half2*>(&u3.y));
            acc.x += w0 * a0.x + w1 * a1.x + w2 * a2.x + w3 * a3.x;
            acc.y += w0 * a0.y + w1 * a1.y + w2 * a2.y + w3 * a3.y;
            acc.z += w0 * b0.x + w1 * b1.x + w2 * b2.x + w3 * b3.x;
            acc.w += w0 * b0.y + w1 * b1.y + w2 * b2.y + w3 * b3.y;
        }
        for (; k < m; k++) {
            int   d = __shfl_sync(0xffffffffu, dv, k);
            float w = __shfl_sync(0xffffffffu, wv, k);
            uint2 u = g_X0h[(size_t)d * 32 + lane];
            float2 a = __half22float2(*reinterpret_cast<__half2*>(&u.x));
            float2 c = __half22float2(*reinterpret_cast<__half2*>(&u.y));
            acc.x += w * a.x;
            acc.y += w * a.y;
            acc.z += w * c.x;
            acc.w += w * c.y;
        }
    }

    float4 bb = __ldg(b4 + lane);
    acc.x = fmaxf(acc.x + bb.x, 0.f);
    acc.y = fmaxf(acc.y + bb.y, 0.f);
    acc.z = fmaxf(acc.z + bb.z, 0.f);
    acc.w = fmaxf(acc.w + bb.w, 0.f);
    out4[(size_t)node * 32 + lane] = acc;
}

// ---------------------------------------------------------------------------
extern "C" void kernel_launch(void* const* d_in, const int* in_sizes, int n_in,
                              void* d_out, int out_size)
{
    const float* notes = (const float*)d_in[0];
    const float* w     = (const float*)d_in[1];
    const float* b     = (const float*)d_in[2];
    const int*   esrc  = (const int*)  d_in[3];
    const int*   edst  = (const int*)  d_in[4];
    const float* ew    = (const float*)d_in[5];

    const int H = in_sizes[2];
    const int D = in_sizes[1] / H;
    const int N = in_sizes[0] / D;
    const int E = in_sizes[3];
    const int g = 2 * N - out_size / H;

    float4* out4 = (float4*)d_out;
    const int NB = (N + SCAN_BLK - 1) / SCAN_BLK;

    cudaFuncSetAttribute(gemm_kernel,
                         cudaFuncAttributeMaxDynamicSharedMemorySize,
                         SMEM_BYTES);

    hist_kernel<<<592, 256>>>(esrc, E);
    scan_kernel<<<NB, 256>>>(N, E);
    scatter_kernel<<<592, 256>>>(esrc, edst, ew, E);

    gemm_kernel<<<(N + BM - 1) / BM, 256, SMEM_BYTES>>>(
        (const float4*)notes, (const float4*)w, out4, N, g);

    gather_kernel<<<(N * 32 + 255) / 256, 256>>>(
        (const float4*)b, out4, N);
}

// round 10
// speedup vs baseline: 1.0891x; 1.0891x over previous
#include <cuda_runtime.h>
#include <cuda_fp16.h>
#include <cuda_bf16.h>
#include <mma.h>

using namespace nvcuda;

// ---------------------------------------------------------------------------
// PhysicsConvolution: X0 = notes@w ; X1 = segment_sum(ew * X0[dst], src) ;
// out = concat(relu(X1 + b), X0[garment:])
//
// R10 = R8 (145.2us: BM=64 split-fp16 HMMA GEMM, fused-scan CSR) + ONE
// change: gather uses 2 nodes/warp, half-warp per node, uint4 (LDG.128)
// row loads.
// ---------------------------------------------------------------------------

#define HD   128
#define BM   64
#define PAD  136

#define MAXN 131072
#define MAXE 1700000
#define SCAN_BLK 1024

#define SMEM_BYTES ((2 * HD * PAD + 2 * BM * PAD) * 2)   // 102 KB

__device__ uint4  g_X0q[2200000];       // fp16 X0: [N][16] uint4 (8 halves each)
__device__ int2   g_sdw[MAXE];          // CSR payload {dst, w}
__device__ int    g_cnt[MAXN + 1];      // zero at load; scan restores zeros
__device__ int    g_off[MAXN + 2];
__device__ int    g_cur[MAXN + 1];
__device__ unsigned long long g_agg[256]; // lookback flags; scatter resets

// ---------------------------------------------------------------------------
// GEMM via split-fp16 HMMA (identical to R8).  Block: 8 warps, 64x128 tile,
// warp tile 16x64.  W split fp32->hi/lo in smem.
// ---------------------------------------------------------------------------
__global__ __launch_bounds__(256) void gemm_kernel(
    const float4* __restrict__ A4,
    const float4* __restrict__ W4,
    float4* __restrict__ out4,
    int N, int g)
{
    extern __shared__ char smem[];
    __half* sWh = reinterpret_cast<__half*>(smem);        // HD x PAD
    __half* sWl = sWh + HD * PAD;                         // HD x PAD
    __half* sAh = sWl + HD * PAD;                         // BM x PAD
    __half* sAl = sAh + BM * PAD;                         // BM x PAD
    float*  sC  = reinterpret_cast<float*>(sAh);          // BM x HD (aliases A)

    const int tid  = threadIdx.x;
    const int row0 = blockIdx.x * BM;

    #pragma unroll
    for (int i = tid; i < HD * 32; i += 256) {
        int row = i >> 5, c4 = (i & 31) * 4;
        float4 wv = W4[i];
        __half hv[4], lv[4];
        #pragma unroll
        for (int u = 0; u < 4; u++) {
            float  v  = (&wv.x)[u];
            __half hi = __float2half_rn(v);
            hv[u] = hi;
            lv[u] = __float2half_rn(v - __half2float(hi));
        }
        *reinterpret_cast<uint2*>(sWh + row * PAD + c4) =
            *reinterpret_cast<uint2*>(hv);
        *reinterpret_cast<uint2*>(sWl + row * PAD + c4) =
            *reinterpret_cast<uint2*>(lv);
    }

    #pragma unroll
    for (int i = tid; i < BM * 32; i += 256) {
        int rl = i >> 5, c4 = (i & 31) * 4;
        int r  = row0 + rl;
        float4 a = (r < N) ? A4[(size_t)r * 32 + (i & 31)]
                           : make_float4(0.f, 0.f, 0.f, 0.f);
        __half hv[4], lv[4];
        #pragma unroll
        for (int u = 0; u < 4; u++) {
            float  v  = (&a.x)[u];
            __half hi = __float2half_rn(v);
            hv[u] = hi;
            lv[u] = __float2half_rn(v - __half2float(hi));
        }
        *reinterpret_cast<uint2*>(sAh + rl * PAD + c4) =
            *reinterpret_cast<uint2*>(hv);
        *reinterpret_cast<uint2*>(sAl + rl * PAD + c4) =
            *reinterpret_cast<uint2*>(lv);
    }
    __syncthreads();

    const int wid = tid >> 5;
    const int wr  = wid >> 1;
    const int wc  = wid & 1;

    wmma::fragment<wmma::accumulator, 16, 16, 16, float> acc[4];
    #pragma unroll
    for (int j = 0; j < 4; j++) wmma::fill_fragment(acc[j], 0.f);

    #pragma unroll
    for (int k = 0; k < 8; k++) {
        const int k0 = k * 16;
        wmma::fragment<wmma::matrix_a, 16, 16, 16, __half, wmma::row_major> ah, al;
        wmma::load_matrix_sync(ah, sAh + (wr * 16) * PAD + k0, PAD);
        wmma::load_matrix_sync(al, sAl + (wr * 16) * PAD + k0, PAD);
        #pragma unroll
        for (int j = 0; j < 4; j++) {
            const int col = wc * 64 + j * 16;
            wmma::fragment<wmma::matrix_b, 16, 16, 16, __half, wmma::row_major> bh, bl;
            wmma::load_matrix_sync(bh, sWh + k0 * PAD + col, PAD);
            wmma::load_matrix_sync(bl, sWl + k0 * PAD + col, PAD);
            wmma::mma_sync(acc[j], ah, bh, acc[j]);
            wmma::mma_sync(acc[j], ah, bl, acc[j]);
            wmma::mma_sync(acc[j], al, bh, acc[j]);
        }
    }

    __syncthreads();
    #pragma unroll
    for (int j = 0; j < 4; j++)
        wmma::store_matrix_sync(sC + (wr * 16) * HD + wc * 64 + j * 16,
                                acc[j], HD, wmma::mem_row_major);
    __syncthreads();

    const int tx = tid & 31;
    const int ty = tid >> 5;
    #pragma unroll
    for (int i = 0; i < 8; i++) {
        int rl = ty * 8 + i;
        int r  = row0 + rl;
        if (r < N) {
            float4 v = *reinterpret_cast<float4*>(sC + rl * HD + tx * 4);
            __half2 lo = __float22half2_rn(make_float2(v.x, v.y));
            __half2 hi = __float22half2_rn(make_float2(v.z, v.w));
            uint2 p;
            p.x = *reinterpret_cast<unsigned*>(&lo);
            p.y = *reinterpret_cast<unsigned*>(&hi);
            reinterpret_cast<uint2*>(g_X0q)[(size_t)r * 32 + tx] = p;
            if (r >= g)
                out4[(size_t)(N + r - g) * 32 + tx] = v;
        }
    }
}

// ---------------------------------------------------------------------------
__global__ void hist_kernel(const int* __restrict__ esrc, int E) {
    for (int e = blockIdx.x * blockDim.x + threadIdx.x; e < E;
         e += gridDim.x * blockDim.x)
        atomicAdd(&g_cnt[esrc[e]], 1);
}

// ---------------------------------------------------------------------------
// Fused exclusive scan (decoupled lookback), identical to R8.
// ---------------------------------------------------------------------------
__global__ __launch_bounds__(256) void scan_kernel(int N, int E) {
    __shared__ int ssum[256];
    __shared__ int s_bpre;
    const int t   = threadIdx.x;
    const int bid = blockIdx.x;
    const int base = bid * SCAN_BLK + t * 4;

    int c0 = 0, c1 = 0, c2 = 0, c3 = 0;
    if (base + 0 < N) { c0 = g_cnt[base + 0]; g_cnt[base + 0] = 0; }
    if (base + 1 < N) { c1 = g_cnt[base + 1]; g_cnt[base + 1] = 0; }
    if (base + 2 < N) { c2 = g_cnt[base + 2]; g_cnt[base + 2] = 0; }
    if (base + 3 < N) { c3 = g_cnt[base + 3]; g_cnt[base + 3] = 0; }
    int tot = c0 + c1 + c2 + c3;

    ssum[t] = tot;
    __syncthreads();
    #pragma unroll
    for (int off = 1; off < 256; off <<= 1) {
        int v = (t >= off) ? ssum[t - off] : 0;
        __syncthreads();
        ssum[t] += v;
        __syncthreads();
    }
    int ex = ssum[t] - tot;

    if (t == 0)
        atomicExch(&g_agg[bid], (1ULL << 32) | (unsigned)ssum[255]);

    if (t < 32) {
        int prefix = 0;
        for (int ws = 0; ws < bid; ws += 32) {
            int j = ws + t;
            unsigned val = 0;
            if (j < bid) {
                unsigned long long v;
                do { v = atomicAdd(&g_agg[j], 0ULL); } while (!(v >> 32));
                val = (unsigned)v;
            }
            #pragma unroll
            for (int o = 16; o; o >>= 1)
                val += __shfl_down_sync(0xffffffffu, val, o);
            if (t == 0) prefix += (int)val;
        }
        if (t == 0) s_bpre = prefix;
    }
    __syncthreads();

    const int boff = s_bpre;
    if (base + 0 < N) { int v = ex + boff;                g_off[base + 0] = v; g_cur[base + 0] = v; }
    if (base + 1 < N) { int v = ex + c0 + boff;           g_off[base + 1] = v; g_cur[base + 1] = v; }
    if (base + 2 < N) { int v = ex + c0 + c1 + boff;      g_off[base + 2] = v; g_cur[base + 2] = v; }
    if (base + 3 < N) { int v = ex + c0 + c1 + c2 + boff; g_off[base + 3] = v; g_cur[base + 3] = v; }
    if (bid == 0 && t == 0) g_off[N] = E;
}

// ---------------------------------------------------------------------------
__global__ void scatter_kernel(const int* __restrict__ esrc,
                               const int* __restrict__ edst,
                               const float* __restrict__ ew, int E) {
    if (blockIdx.x == 0 && threadIdx.x < 256)
        g_agg[threadIdx.x] = 0ULL;
    for (int e = blockIdx.x * blockDim.x + threadIdx.x; e < E;
         e += gridDim.x * blockDim.x) {
        int s = esrc[e];
        int p = atomicAdd(&g_cur[s], 1);
        g_sdw[p] = make_int2(edst[e], __float_as_int(ew[e]));
    }
}

// ---------------------------------------------------------------------------
// Gather: 2 nodes per warp, half-warp (16 lanes) per node, uint4 row loads.
// Warp-uniform outer loop over max(cnt0, cnt1); finished half predicates
// off its loads.  fp32 accumulate, fused bias+relu -> out head.
// ---------------------------------------------------------------------------
__global__ __launch_bounds__(256) void gather_kernel(
    const float4* __restrict__ b4,
    float4* __restrict__ out4,
    int N)
{
    const int lane = threadIdx.x & 31;
    const int sub  = lane >> 4;          // half-warp id: 0 / 1
    const int hl   = lane & 15;          // lane within half: covers 8 cols
    const int wnum = (blockIdx.x * blockDim.x + threadIdx.x) >> 5;
    const int node = wnum * 2 + sub;
    const bool active = node < N;
    const int  vnode  = active ? node : N - 1;

    const int start = g_off[vnode];
    const int cnt   = active ? (g_off[vnode + 1] - start) : 0;

    // warp-uniform trip count
    const int ocnt   = __shfl_xor_sync(0xffffffffu, cnt, 16);
    const int maxcnt = max(cnt, ocnt);

    float acc[8];
    #pragma unroll
    for (int i = 0; i < 8; i++) acc[i] = 0.f;

    for (int it = 0; it < maxcnt; it += 16) {
        const int m  = min(16, cnt - it);          // per-half valid count
        const int mu = min(16, maxcnt - it);       // warp-uniform bound
        int   dv = 0;
        float wv = 0.f;
        if (hl < m) {
            int2 p = g_sdw[start + it + hl];
            dv = p.x;
            wv = __int_as_float(p.y);
        }
        for (int k = 0; k < mu; k++) {
            int   d = __shfl_sync(0xffffffffu, dv, sub * 16 + k);
            float w = __shfl_sync(0xffffffffu, wv, sub * 16 + k);
            if (k < m) {
                uint4 u = g_X0q[(size_t)d * 16 + hl];
                float2 f0 = __half22float2(*reinterpret_cast<__half2*>(&u.x));
                float2 f1 = __half22float2(*reinterpret_cast<__half2*>(&u.y));
                float2 f2 = __half22float2(*reinterpret_cast<__half2*>(&u.z));
                float2 f3 = __half22float2(*reinterpret_cast<__half2*>(&u.w));
                acc[0] += w * f0.x;  acc[1] += w * f0.y;
                acc[2] += w * f1.x;  acc[3] += w * f1.y;
                acc[4] += w * f2.x;  acc[5] += w * f2.y;
                acc[6] += w * f3.x;  acc[7] += w * f3.y;
            }
        }
    }

    if (active) {
        float4 b0 = __ldg(b4 + hl * 2 + 0);
        float4 b1 = __ldg(b4 + hl * 2 + 1);
        float4 v0 = make_float4(fmaxf(acc[0] + b0.x, 0.f),
                                fmaxf(acc[1] + b0.y, 0.f),
                                fmaxf(acc[2] + b0.z, 0.f),
                                fmaxf(acc[3] + b0.w, 0.f));
        float4 v1 = make_float4(fmaxf(acc[4] + b1.x, 0.f),
                                fmaxf(acc[5] + b1.y, 0.f),
                                fmaxf(acc[6] + b1.z, 0.f),
                                fmaxf(acc[7] + b1.w, 0.f));
        out4[(size_t)node * 32 + hl * 2 + 0] = v0;
        out4[(size_t)node * 32 + hl * 2 + 1] = v1;
    }
}

// ---------------------------------------------------------------------------
extern "C" void kernel_launch(void* const* d_in, const int* in_sizes, int n_in,
                              void* d_out, int out_size)
{
    const float* notes = (const float*)d_in[0];
    const float* w     = (const float*)d_in[1];
    const float* b     = (const float*)d_in[2];
    const int*   esrc  = (const int*)  d_in[3];
    const int*   edst  = (const int*)  d_in[4];
    const float* ew    = (const float*)d_in[5];

    const int H = in_sizes[2];
    const int D = in_sizes[1] / H;
    const int N = in_sizes[0] / D;
    const int E = in_sizes[3];
    const int g = 2 * N - out_size / H;

    float4* out4 = (float4*)d_out;
    const int NB = (N + SCAN_BLK - 1) / SCAN_BLK;

    cudaFuncSetAttribute(gemm_kernel,
                         cudaFuncAttributeMaxDynamicSharedMemorySize,
                         SMEM_BYTES);

    hist_kernel<<<592, 256>>>(esrc, E);
    scan_kernel<<<NB, 256>>>(N, E);
    scatter_kernel<<<592, 256>>>(esrc, edst, ew, E);

    gemm_kernel<<<(N + BM - 1) / BM, 256, SMEM_BYTES>>>(
        (const float4*)notes, (const float4*)w, out4, N, g);

    // 2 nodes per warp -> 16 nodes per 256-thread block
    gather_kernel<<<(N + 15) / 16, 256>>>(
        (const float4*)b, out4, N);
}

// round 11
// speedup vs baseline: 1.1598x; 1.0650x over previous
#include <cuda_runtime.h>
#include <cuda_fp16.h>
#include <cuda_bf16.h>
#include <mma.h>

using namespace nvcuda;

// ---------------------------------------------------------------------------
// PhysicsConvolution: X0 = notes@w ; X1 = segment_sum(ew * X0[dst], src) ;
// out = concat(relu(X1 + b), X0[garment:])
//
// R11 = R10 (138.0us) + ONE change: GEMM 3-term split -> 2-term
// (X0 = Ah@Wh + Al@Wh = A@Wh; ~2.8e-4 rel err, same order as the fp16 X0
// storage error already present).  -40% fragment loads, -33% MMAs, W-lo
// staging removed (smem 102 -> 69.6 KB).
// ---------------------------------------------------------------------------

#define HD   128
#define BM   64
#define PAD  136

#define MAXN 131072
#define MAXE 1700000
#define SCAN_BLK 1024

#define SMEM_BYTES ((HD * PAD + 2 * BM * PAD) * 2)   // 69632 B

__device__ uint4  g_X0q[2200000];       // fp16 X0: [N][16] uint4 (8 halves each)
__device__ int2   g_sdw[MAXE];          // CSR payload {dst, w}
__device__ int    g_cnt[MAXN + 1];      // zero at load; scan restores zeros
__device__ int    g_off[MAXN + 2];
__device__ int    g_cur[MAXN + 1];
__device__ unsigned long long g_agg[256]; // lookback flags; scatter resets

// ---------------------------------------------------------------------------
// GEMM: X0 = A@Wh via 2-term fp16 HMMA (A = Ah + Al exact split).
// Block: 8 warps, 64x128 tile, warp tile 16x64.
// ---------------------------------------------------------------------------
__global__ __launch_bounds__(256) void gemm_kernel(
    const float4* __restrict__ A4,
    const float4* __restrict__ W4,
    float4* __restrict__ out4,
    int N, int g)
{
    extern __shared__ char smem[];
    __half* sWh = reinterpret_cast<__half*>(smem);        // HD x PAD
    __half* sAh = sWh + HD * PAD;                         // BM x PAD
    __half* sAl = sAh + BM * PAD;                         // BM x PAD
    float*  sC  = reinterpret_cast<float*>(sAh);          // BM x HD (aliases A)

    const int tid  = threadIdx.x;
    const int row0 = blockIdx.x * BM;

    // Stage W hi-part only.
    #pragma unroll
    for (int i = tid; i < HD * 32; i += 256) {
        int row = i >> 5, c4 = (i & 31) * 4;
        float4 wv = W4[i];
        __half hv[4];
        #pragma unroll
        for (int u = 0; u < 4; u++) hv[u] = __float2half_rn((&wv.x)[u]);
        *reinterpret_cast<uint2*>(sWh + row * PAD + c4) =
            *reinterpret_cast<uint2*>(hv);
    }

    // Stage A tile: fp32 -> (hi, lo) exact fp16 split.
    #pragma unroll
    for (int i = tid; i < BM * 32; i += 256) {
        int rl = i >> 5, c4 = (i & 31) * 4;
        int r  = row0 + rl;
        float4 a = (r < N) ? A4[(size_t)r * 32 + (i & 31)]
                           : make_float4(0.f, 0.f, 0.f, 0.f);
        __half hv[4], lv[4];
        #pragma unroll
        for (int u = 0; u < 4; u++) {
            float  v  = (&a.x)[u];
            __half hi = __float2half_rn(v);
            hv[u] = hi;
            lv[u] = __float2half_rn(v - __half2float(hi));
        }
        *reinterpret_cast<uint2*>(sAh + rl * PAD + c4) =
            *reinterpret_cast<uint2*>(hv);
        *reinterpret_cast<uint2*>(sAl + rl * PAD + c4) =
            *reinterpret_cast<uint2*>(lv);
    }
    __syncthreads();

    const int wid = tid >> 5;
    const int wr  = wid >> 1;
    const int wc  = wid & 1;

    wmma::fragment<wmma::accumulator, 16, 16, 16, float> acc[4];
    #pragma unroll
    for (int j = 0; j < 4; j++) wmma::fill_fragment(acc[j], 0.f);

    #pragma unroll
    for (int k = 0; k < 8; k++) {
        const int k0 = k * 16;
        wmma::fragment<wmma::matrix_a, 16, 16, 16, __half, wmma::row_major> ah, al;
        wmma::load_matrix_sync(ah, sAh + (wr * 16) * PAD + k0, PAD);
        wmma::load_matrix_sync(al, sAl + (wr * 16) * PAD + k0, PAD);
        #pragma unroll
        for (int j = 0; j < 4; j++) {
            const int col = wc * 64 + j * 16;
            wmma::fragment<wmma::matrix_b, 16, 16, 16, __half, wmma::row_major> bh;
            wmma::load_matrix_sync(bh, sWh + k0 * PAD + col, PAD);
            wmma::mma_sync(acc[j], ah, bh, acc[j]);
            wmma::mma_sync(acc[j], al, bh, acc[j]);
        }
    }

    __syncthreads();   // done reading A region; reuse as fp32 C
    #pragma unroll
    for (int j = 0; j < 4; j++)
        wmma::store_matrix_sync(sC + (wr * 16) * HD + wc * 64 + j * 16,
                                acc[j], HD, wmma::mem_row_major);
    __syncthreads();

    const int tx = tid & 31;
    const int ty = tid >> 5;
    #pragma unroll
    for (int i = 0; i < 8; i++) {
        int rl = ty * 8 + i;
        int r  = row0 + rl;
        if (r < N) {
            float4 v = *reinterpret_cast<float4*>(sC + rl * HD + tx * 4);
            __half2 lo = __float22half2_rn(make_float2(v.x, v.y));
            __half2 hi = __float22half2_rn(make_float2(v.z, v.w));
            uint2 p;
            p.x = *reinterpret_cast<unsigned*>(&lo);
            p.y = *reinterpret_cast<unsigned*>(&hi);
            reinterpret_cast<uint2*>(g_X0q)[(size_t)r * 32 + tx] = p;
            if (r >= g)
                out4[(size_t)(N + r - g) * 32 + tx] = v;
        }
    }
}

// ---------------------------------------------------------------------------
__global__ void hist_kernel(const int* __restrict__ esrc, int E) {
    for (int e = blockIdx.x * blockDim.x + threadIdx.x; e < E;
         e += gridDim.x * blockDim.x)
        atomicAdd(&g_cnt[esrc[e]], 1);
}

// ---------------------------------------------------------------------------
// Fused exclusive scan (decoupled lookback), identical to R10.
// ---------------------------------------------------------------------------
__global__ __launch_bounds__(256) void scan_kernel(int N, int E) {
    __shared__ int ssum[256];
    __shared__ int s_bpre;
    const int t   = threadIdx.x;
    const int bid = blockIdx.x;
    const int base = bid * SCAN_BLK + t * 4;

    int c0 = 0, c1 = 0, c2 = 0, c3 = 0;
    if (base + 0 < N) { c0 = g_cnt[base + 0]; g_cnt[base + 0] = 0; }
    if (base + 1 < N) { c1 = g_cnt[base + 1]; g_cnt[base + 1] = 0; }
    if (base + 2 < N) { c2 = g_cnt[base + 2]; g_cnt[base + 2] = 0; }
    if (base + 3 < N) { c3 = g_cnt[base + 3]; g_cnt[base + 3] = 0; }
    int tot = c0 + c1 + c2 + c3;

    ssum[t] = tot;
    __syncthreads();
    #pragma unroll
    for (int off = 1; off < 256; off <<= 1) {
        int v = (t >= off) ? ssum[t - off] : 0;
        __syncthreads();
        ssum[t] += v;
        __syncthreads();
    }
    int ex = ssum[t] - tot;

    if (t == 0)
        atomicExch(&g_agg[bid], (1ULL << 32) | (unsigned)ssum[255]);

    if (t < 32) {
        int prefix = 0;
        for (int ws = 0; ws < bid; ws += 32) {
            int j = ws + t;
            unsigned val = 0;
            if (j < bid) {
                unsigned long long v;
                do { v = atomicAdd(&g_agg[j], 0ULL); } while (!(v >> 32));
                val = (unsigned)v;
            }
            #pragma unroll
            for (int o = 16; o; o >>= 1)
                val += __shfl_down_sync(0xffffffffu, val, o);
            if (t == 0) prefix += (int)val;
        }
        if (t == 0) s_bpre = prefix;
    }
    __syncthreads();

    const int boff = s_bpre;
    if (base + 0 < N) { int v = ex + boff;                g_off[base + 0] = v; g_cur[base + 0] = v; }
    if (base + 1 < N) { int v = ex + c0 + boff;           g_off[base + 1] = v; g_cur[base + 1] = v; }
    if (base + 2 < N) { int v = ex + c0 + c1 + boff;      g_off[base + 2] = v; g_cur[base + 2] = v; }
    if (base + 3 < N) { int v = ex + c0 + c1 + c2 + boff; g_off[base + 3] = v; g_cur[base + 3] = v; }
    if (bid == 0 && t == 0) g_off[N] = E;
}

// ---------------------------------------------------------------------------
__global__ void scatter_kernel(const int* __restrict__ esrc,
                               const int* __restrict__ edst,
                               const float* __restrict__ ew, int E) {
    if (blockIdx.x == 0 && threadIdx.x < 256)
        g_agg[threadIdx.x] = 0ULL;
    for (int e = blockIdx.x * blockDim.x + threadIdx.x; e < E;
         e += gridDim.x * blockDim.x) {
        int s = esrc[e];
        int p = atomicAdd(&g_cur[s], 1);
        g_sdw[p] = make_int2(edst[e], __float_as_int(ew[e]));
    }
}

// ---------------------------------------------------------------------------
// Gather (identical to R10): 2 nodes/warp, half-warp per node, uint4 loads.
// ---------------------------------------------------------------------------
__global__ __launch_bounds__(256) void gather_kernel(
    const float4* __restrict__ b4,
    float4* __restrict__ out4,
    int N)
{
    const int lane = threadIdx.x & 31;
    const int sub  = lane >> 4;
    const int hl   = lane & 15;
    const int wnum = (blockIdx.x * blockDim.x + threadIdx.x) >> 5;
    const int node = wnum * 2 + sub;
    const bool active = node < N;
    const int  vnode  = active ? node : N - 1;

    const int start = g_off[vnode];
    const int cnt   = active ? (g_off[vnode + 1] - start) : 0;

    const int ocnt   = __shfl_xor_sync(0xffffffffu, cnt, 16);
    const int maxcnt = max(cnt, ocnt);

    float acc[8];
    #pragma unroll
    for (int i = 0; i < 8; i++) acc[i] = 0.f;

    for (int it = 0; it < maxcnt; it += 16) {
        const int m  = min(16, cnt - it);
        const int mu = min(16, maxcnt - it);
        int   dv = 0;
        float wv = 0.f;
        if (hl < m) {
            int2 p = g_sdw[start + it + hl];
            dv = p.x;
            wv = __int_as_float(p.y);
        }
        for (int k = 0; k < mu; k++) {
            int   d = __shfl_sync(0xffffffffu, dv, sub * 16 + k);
            float w = __shfl_sync(0xffffffffu, wv, sub * 16 + k);
            if (k < m) {
                uint4 u = g_X0q[(size_t)d * 16 + hl];
                float2 f0 = __half22float2(*reinterpret_cast<__half2*>(&u.x));
                float2 f1 = __half22float2(*reinterpret_cast<__half2*>(&u.y));
                float2 f2 = __half22float2(*reinterpret_cast<__half2*>(&u.z));
                float2 f3 = __half22float2(*reinterpret_cast<__half2*>(&u.w));
                acc[0] += w * f0.x;  acc[1] += w * f0.y;
                acc[2] += w * f1.x;  acc[3] += w * f1.y;
                acc[4] += w * f2.x;  acc[5] += w * f2.y;
                acc[6] += w * f3.x;  acc[7] += w * f3.y;
            }
        }
    }

    if (active) {
        float4 b0 = __ldg(b4 + hl * 2 + 0);
        float4 b1 = __ldg(b4 + hl * 2 + 1);
        float4 v0 = make_float4(fmaxf(acc[0] + b0.x, 0.f),
                                fmaxf(acc[1] + b0.y, 0.f),
                                fmaxf(acc[2] + b0.z, 0.f),
                                fmaxf(acc[3] + b0.w, 0.f));
        float4 v1 = make_float4(fmaxf(acc[4] + b1.x, 0.f),
                                fmaxf(acc[5] + b1.y, 0.f),
                                fmaxf(acc[6] + b1.z, 0.f),
                                fmaxf(acc[7] + b1.w, 0.f));
        out4[(size_t)node * 32 + hl * 2 + 0] = v0;
        out4[(size_t)node * 32 + hl * 2 + 1] = v1;
    }
}

// ---------------------------------------------------------------------------
extern "C" void kernel_launch(void* const* d_in, const int* in_sizes, int n_in,
                              void* d_out, int out_size)
{
    const float* notes = (const float*)d_in[0];
    const float* w     = (const float*)d_in[1];
    const float* b     = (const float*)d_in[2];
    const int*   esrc  = (const int*)  d_in[3];
    const int*   edst  = (const int*)  d_in[4];
    const float* ew    = (const float*)d_in[5];

    const int H = in_sizes[2];
    const int D = in_sizes[1] / H;
    const int N = in_sizes[0] / D;
    const int E = in_sizes[3];
    const int g = 2 * N - out_size / H;

    float4* out4 = (float4*)d_out;
    const int NB = (N + SCAN_BLK - 1) / SCAN_BLK;

    cudaFuncSetAttribute(gemm_kernel,
                         cudaFuncAttributeMaxDynamicSharedMemorySize,
                         SMEM_BYTES);

    hist_kernel<<<592, 256>>>(esrc, E);
    scan_kernel<<<NB, 256>>>(N, E);
    scatter_kernel<<<592, 256>>>(esrc, edst, ew, E);

    gemm_kernel<<<(N + BM - 1) / BM, 256, SMEM_BYTES>>>(
        (const float4*)notes, (const float4*)w, out4, N, g);

    gather_kernel<<<(N + 15) / 16, 256>>>(
        (const float4*)b, out4, N);
}

// round 12
// speedup vs baseline: 1.1796x; 1.0171x over previous
#include <cuda_runtime.h>
#include <cuda_fp16.h>
#include <cuda_bf16.h>
#include <mma.h>

using namespace nvcuda;

// ---------------------------------------------------------------------------
// PhysicsConvolution: X0 = notes@w ; X1 = segment_sum(ew * X0[dst], src) ;
// out = concat(relu(X1 + b), X0[garment:])
//
// R12 = R11 (129.5us) + ONE change: GEMM 2-term -> 1-term pure fp16
// (X0 = Ah@Wh).  Measured error model: fp16-storage 2.0e-4 (+) Wh 2.0e-4
// (+) Ah 2.0e-4 (quadrature) -> ~3.5e-4, still 3x under the 1e-3 gate.
// MMAs halve, sAl staging deleted (smem 69.6 -> 51 KB, 4 blocks/SM).
// ---------------------------------------------------------------------------

#define HD   128
#define BM   64
#define PAD  136

#define MAXN 131072
#define MAXE 1700000
#define SCAN_BLK 1024

#define SMEM_BYTES ((HD * PAD + BM * PAD) * 2)   // 52224 B

__device__ uint4  g_X0q[2200000];       // fp16 X0: [N][16] uint4 (8 halves each)
__device__ int2   g_sdw[MAXE];          // CSR payload {dst, w}
__device__ int    g_cnt[MAXN + 1];      // zero at load; scan restores zeros
__device__ int    g_off[MAXN + 2];
__device__ int    g_cur[MAXN + 1];
__device__ unsigned long long g_agg[256]; // lookback flags; scatter resets

// ---------------------------------------------------------------------------
// GEMM: X0 = Ah@Wh, fp16 operands, fp32 accumulate.
// Block: 8 warps, 64x128 tile, warp tile 16x64.
// fp32 C epilogue aliases the sWh region (W dead after the MMA sync).
// ---------------------------------------------------------------------------
__global__ __launch_bounds__(256) void gemm_kernel(
    const float4* __restrict__ A4,
    const float4* __restrict__ W4,
    float4* __restrict__ out4,
    int N, int g)
{
    extern __shared__ char smem[];
    __half* sWh = reinterpret_cast<__half*>(smem);        // HD x PAD (34.8 KB)
    __half* sAh = sWh + HD * PAD;                         // BM x PAD (17.4 KB)
    float*  sC  = reinterpret_cast<float*>(smem);         // BM x HD (32 KB, aliases W)

    const int tid  = threadIdx.x;
    const int row0 = blockIdx.x * BM;

    // Stage W hi-part.
    #pragma unroll
    for (int i = tid; i < HD * 32; i += 256) {
        int row = i >> 5, c4 = (i & 31) * 4;
        float4 wv = W4[i];
        __half hv[4];
        #pragma unroll
        for (int u = 0; u < 4; u++) hv[u] = __float2half_rn((&wv.x)[u]);
        *reinterpret_cast<uint2*>(sWh + row * PAD + c4) =
            *reinterpret_cast<uint2*>(hv);
    }

    // Stage A tile hi-part.
    #pragma unroll
    for (int i = tid; i < BM * 32; i += 256) {
        int rl = i >> 5, c4 = (i & 31) * 4;
        int r  = row0 + rl;
        float4 a = (r < N) ? A4[(size_t)r * 32 + (i & 31)]
                           : make_float4(0.f, 0.f, 0.f, 0.f);
        __half hv[4];
        #pragma unroll
        for (int u = 0; u < 4; u++) hv[u] = __float2half_rn((&a.x)[u]);
        *reinterpret_cast<uint2*>(sAh + rl * PAD + c4) =
            *reinterpret_cast<uint2*>(hv);
    }
    __syncthreads();

    const int wid = tid >> 5;
    const int wr  = wid >> 1;
    const int wc  = wid & 1;

    wmma::fragment<wmma::accumulator, 16, 16, 16, float> acc[4];
    #pragma unroll
    for (int j = 0; j < 4; j++) wmma::fill_fragment(acc[j], 0.f);

    #pragma unroll
    for (int k = 0; k < 8; k++) {
        const int k0 = k * 16;
        wmma::fragment<wmma::matrix_a, 16, 16, 16, __half, wmma::row_major> ah;
        wmma::load_matrix_sync(ah, sAh + (wr * 16) * PAD + k0, PAD);
        #pragma unroll
        for (int j = 0; j < 4; j++) {
            const int col = wc * 64 + j * 16;
            wmma::fragment<wmma::matrix_b, 16, 16, 16, __half, wmma::row_major> bh;
            wmma::load_matrix_sync(bh, sWh + k0 * PAD + col, PAD);
            wmma::mma_sync(acc[j], ah, bh, acc[j]);
        }
    }

    __syncthreads();   // W and A reads complete; reuse smem front as fp32 C
    #pragma unroll
    for (int j = 0; j < 4; j++)
        wmma::store_matrix_sync(sC + (wr * 16) * HD + wc * 64 + j * 16,
                                acc[j], HD, wmma::mem_row_major);
    __syncthreads();

    const int tx = tid & 31;
    const int ty = tid >> 5;
    #pragma unroll
    for (int i = 0; i < 8; i++) {
        int rl = ty * 8 + i;
        int r  = row0 + rl;
        if (r < N) {
            float4 v = *reinterpret_cast<float4*>(sC + rl * HD + tx * 4);
            __half2 lo = __float22half2_rn(make_float2(v.x, v.y));
            __half2 hi = __float22half2_rn(make_float2(v.z, v.w));
            uint2 p;
            p.x = *reinterpret_cast<unsigned*>(&lo);
            p.y = *reinterpret_cast<unsigned*>(&hi);
            reinterpret_cast<uint2*>(g_X0q)[(size_t)r * 32 + tx] = p;
            if (r >= g)
                out4[(size_t)(N + r - g) * 32 + tx] = v;
        }
    }
}

// ---------------------------------------------------------------------------
__global__ void hist_kernel(const int* __restrict__ esrc, int E) {
    for (int e = blockIdx.x * blockDim.x + threadIdx.x; e < E;
         e += gridDim.x * blockDim.x)
        atomicAdd(&g_cnt[esrc[e]], 1);
}

// ---------------------------------------------------------------------------
// Fused exclusive scan (decoupled lookback), identical to R11.
// ---------------------------------------------------------------------------
__global__ __launch_bounds__(256) void scan_kernel(int N, int E) {
    __shared__ int ssum[256];
    __shared__ int s_bpre;
    const int t   = threadIdx.x;
    const int bid = blockIdx.x;
    const int base = bid * SCAN_BLK + t * 4;

    int c0 = 0, c1 = 0, c2 = 0, c3 = 0;
    if (base + 0 < N) { c0 = g_cnt[base + 0]; g_cnt[base + 0] = 0; }
    if (base + 1 < N) { c1 = g_cnt[base + 1]; g_cnt[base + 1] = 0; }
    if (base + 2 < N) { c2 = g_cnt[base + 2]; g_cnt[base + 2] = 0; }
    if (base + 3 < N) { c3 = g_cnt[base + 3]; g_cnt[base + 3] = 0; }
    int tot = c0 + c1 + c2 + c3;

    ssum[t] = tot;
    __syncthreads();
    #pragma unroll
    for (int off = 1; off < 256; off <<= 1) {
        int v = (t >= off) ? ssum[t - off] : 0;
        __syncthreads();
        ssum[t] += v;
        __syncthreads();
    }
    int ex = ssum[t] - tot;

    if (t == 0)
        atomicExch(&g_agg[bid], (1ULL << 32) | (unsigned)ssum[255]);

    if (t < 32) {
        int prefix = 0;
        for (int ws = 0; ws < bid; ws += 32) {
            int j = ws + t;
            unsigned val = 0;
            if (j < bid) {
                unsigned long long v;
                do { v = atomicAdd(&g_agg[j], 0ULL); } while (!(v >> 32));
                val = (unsigned)v;
            }
            #pragma unroll
            for (int o = 16; o; o >>= 1)
                val += __shfl_down_sync(0xffffffffu, val, o);
            if (t == 0) prefix += (int)val;
        }
        if (t == 0) s_bpre = prefix;
    }
    __syncthreads();

    const int boff = s_bpre;
    if (base + 0 < N) { int v = ex + boff;                g_off[base + 0] = v; g_cur[base + 0] = v; }
    if (base + 1 < N) { int v = ex + c0 + boff;           g_off[base + 1] = v; g_cur[base + 1] = v; }
    if (base + 2 < N) { int v = ex + c0 + c1 + boff;      g_off[base + 2] = v; g_cur[base + 2] = v; }
    if (base + 3 < N) { int v = ex + c0 + c1 + c2 + boff; g_off[base + 3] = v; g_cur[base + 3] = v; }
    if (bid == 0 && t == 0) g_off[N] = E;
}

// ---------------------------------------------------------------------------
__global__ void scatter_kernel(const int* __restrict__ esrc,
                               const int* __restrict__ edst,
                               const float* __restrict__ ew, int E) {
    if (blockIdx.x == 0 && threadIdx.x < 256)
        g_agg[threadIdx.x] = 0ULL;
    for (int e = blockIdx.x * blockDim.x + threadIdx.x; e < E;
         e += gridDim.x * blockDim.x) {
        int s = esrc[e];
        int p = atomicAdd(&g_cur[s], 1);
        g_sdw[p] = make_int2(edst[e], __float_as_int(ew[e]));
    }
}

// ---------------------------------------------------------------------------
// Gather (identical to R11): 2 nodes/warp, half-warp per node, uint4 loads.
// ---------------------------------------------------------------------------
__global__ __launch_bounds__(256) void gather_kernel(
    const float4* __restrict__ b4,
    float4* __restrict__ out4,
    int N)
{
    const int lane = threadIdx.x & 31;
    const int sub  = lane >> 4;
    const int hl   = lane & 15;
    const int wnum = (blockIdx.x * blockDim.x + threadIdx.x) >> 5;
    const int node = wnum * 2 + sub;
    const bool active = node < N;
    const int  vnode  = active ? node : N - 1;

    const int start = g_off[vnode];
    const int cnt   = active ? (g_off[vnode + 1] - start) : 0;

    const int ocnt   = __shfl_xor_sync(0xffffffffu, cnt, 16);
    const int maxcnt = max(cnt, ocnt);

    float acc[8];
    #pragma unroll
    for (int i = 0; i < 8; i++) acc[i] = 0.f;

    for (int it = 0; it < maxcnt; it += 16) {
        const int m  = min(16, cnt - it);
        const int mu = min(16, maxcnt - it);
        int   dv = 0;
        float wv = 0.f;
        if (hl < m) {
            int2 p = g_sdw[start + it + hl];
            dv = p.x;
            wv = __int_as_float(p.y);
        }
        for (int k = 0; k < mu; k++) {
            int   d = __shfl_sync(0xffffffffu, dv, sub * 16 + k);
            float w = __shfl_sync(0xffffffffu, wv, sub * 16 + k);
            if (k < m) {
                uint4 u = g_X0q[(size_t)d * 16 + hl];
                float2 f0 = __half22float2(*reinterpret_cast<__half2*>(&u.x));
                float2 f1 = __half22float2(*reinterpret_cast<__half2*>(&u.y));
                float2 f2 = __half22float2(*reinterpret_cast<__half2*>(&u.z));
                float2 f3 = __half22float2(*reinterpret_cast<__half2*>(&u.w));
                acc[0] += w * f0.x;  acc[1] += w * f0.y;
                acc[2] += w * f1.x;  acc[3] += w * f1.y;
                acc[4] += w * f2.x;  acc[5] += w * f2.y;
                acc[6] += w * f3.x;  acc[7] += w * f3.y;
            }
        }
    }

    if (active) {
        float4 b0 = __ldg(b4 + hl * 2 + 0);
        float4 b1 = __ldg(b4 + hl * 2 + 1);
        float4 v0 = make_float4(fmaxf(acc[0] + b0.x, 0.f),
                                fmaxf(acc[1] + b0.y, 0.f),
                                fmaxf(acc[2] + b0.z, 0.f),
                                fmaxf(acc[3] + b0.w, 0.f));
        float4 v1 = make_float4(fmaxf(acc[4] + b1.x, 0.f),
                                fmaxf(acc[5] + b1.y, 0.f),
                                fmaxf(acc[6] + b1.z, 0.f),
                                fmaxf(acc[7] + b1.w, 0.f));
        out4[(size_t)node * 32 + hl * 2 + 0] = v0;
        out4[(size_t)node * 32 + hl * 2 + 1] = v1;
    }
}

// ---------------------------------------------------------------------------
extern "C" void kernel_launch(void* const* d_in, const int* in_sizes, int n_in,
                              void* d_out, int out_size)
{
    const float* notes = (const float*)d_in[0];
    const float* w     = (const float*)d_in[1];
    const float* b     = (const float*)d_in[2];
    const int*   esrc  = (const int*)  d_in[3];
    const int*   edst  = (const int*)  d_in[4];
    const float* ew    = (const float*)d_in[5];

    const int H = in_sizes[2];
    const int D = in_sizes[1] / H;
    const int N = in_sizes[0] / D;
    const int E = in_sizes[3];
    const int g = 2 * N - out_size / H;

    float4* out4 = (float4*)d_out;
    const int NB = (N + SCAN_BLK - 1) / SCAN_BLK;

    cudaFuncSetAttribute(gemm_kernel,
                         cudaFuncAttributeMaxDynamicSharedMemorySize,
                         SMEM_BYTES);

    hist_kernel<<<592, 256>>>(esrc, E);
    scan_kernel<<<NB, 256>>>(N, E);
    scatter_kernel<<<592, 256>>>(esrc, edst, ew, E);

    gemm_kernel<<<(N + BM - 1) / BM, 256, SMEM_BYTES>>>(
        (const float4*)notes, (const float4*)w, out4, N, g);

    gather_kernel<<<(N + 15) / 16, 256>>>(
        (const float4*)b, out4, N);
}

// round 13
// speedup vs baseline: 1.2362x; 1.0479x over previous
#include <cuda_runtime.h>
#include <cuda_fp16.h>
#include <cuda_bf16.h>
#include <mma.h>

using namespace nvcuda;

// ---------------------------------------------------------------------------
// PhysicsConvolution: X0 = notes@w ; X1 = segment_sum(ew * X0[dst], src) ;
// out = concat(relu(X1 + b), X0[garment:])
//
// R13 = R12 (127.4us) + ONE change: GEMM warp tile 16x64 -> 32x64, BM=128
// (0.75 smem loads/MMA; blocks halve -> W staging traffic halves; smem
// 69.6 KB -> 2 blocks/SM, the R8-proven occupancy regime).
// ---------------------------------------------------------------------------

#define HD   128
#define BM   128
#define PAD  136

#define MAXN 131072
#define MAXE 1700000
#define SCAN_BLK 1024

#define SMEM_BYTES ((HD * PAD + BM * PAD) * 2)   // 69632 B

__device__ uint4  g_X0q[2200000];       // fp16 X0: [N][16] uint4 (8 halves each)
__device__ int2   g_sdw[MAXE];          // CSR payload {dst, w}
__device__ int    g_cnt[MAXN + 1];      // zero at load; scan restores zeros
__device__ int    g_off[MAXN + 2];
__device__ int    g_cur[MAXN + 1];
__device__ unsigned long long g_agg[256]; // lookback flags; scatter resets

// ---------------------------------------------------------------------------
// GEMM: X0 = Ah@Wh, fp16 operands, fp32 accumulate.
// Block: 8 warps, 128x128 tile; warp (wr=wid/2, wc=wid&1) covers rows
// wr*32..+31, cols wc*64..+63.  fp32 C epilogue aliases the whole smem.
// ---------------------------------------------------------------------------
__global__ __launch_bounds__(256) void gemm_kernel(
    const float4* __restrict__ A4,
    const float4* __restrict__ W4,
    float4* __restrict__ out4,
    int N, int g)
{
    extern __shared__ char smem[];
    __half* sWh = reinterpret_cast<__half*>(smem);        // HD x PAD (34.8 KB)
    __half* sAh = sWh + HD * PAD;                         // BM x PAD (34.8 KB)
    float*  sC  = reinterpret_cast<float*>(smem);         // BM x HD (64 KB)

    const int tid  = threadIdx.x;
    const int row0 = blockIdx.x * BM;

    // Stage W hi-part.
    #pragma unroll
    for (int i = tid; i < HD * 32; i += 256) {
        int row = i >> 5, c4 = (i & 31) * 4;
        float4 wv = W4[i];
        __half hv[4];
        #pragma unroll
        for (int u = 0; u < 4; u++) hv[u] = __float2half_rn((&wv.x)[u]);
        *reinterpret_cast<uint2*>(sWh + row * PAD + c4) =
            *reinterpret_cast<uint2*>(hv);
    }

    // Stage A tile hi-part.
    #pragma unroll
    for (int i = tid; i < BM * 32; i += 256) {
        int rl = i >> 5, c4 = (i & 31) * 4;
        int r  = row0 + rl;
        float4 a = (r < N) ? A4[(size_t)r * 32 + (i & 31)]
                           : make_float4(0.f, 0.f, 0.f, 0.f);
        __half hv[4];
        #pragma unroll
        for (int u = 0; u < 4; u++) hv[u] = __float2half_rn((&a.x)[u]);
        *reinterpret_cast<uint2*>(sAh + rl * PAD + c4) =
            *reinterpret_cast<uint2*>(hv);
    }
    __syncthreads();

    const int wid = tid >> 5;
    const int wr  = wid >> 1;          // 0..3: rows wr*32..+31
    const int wc  = wid & 1;           // 0..1: cols wc*64..+63

    wmma::fragment<wmma::accumulator, 16, 16, 16, float> acc[2][4];
    #pragma unroll
    for (int r = 0; r < 2; r++)
        #pragma unroll
        for (int j = 0; j < 4; j++) wmma::fill_fragment(acc[r][j], 0.f);

    #pragma unroll
    for (int k = 0; k < 8; k++) {
        const int k0 = k * 16;
        wmma::fragment<wmma::matrix_a, 16, 16, 16, __half, wmma::row_major> ah[2];
        #pragma unroll
        for (int r = 0; r < 2; r++)
            wmma::load_matrix_sync(ah[r], sAh + (wr * 32 + r * 16) * PAD + k0, PAD);
        #pragma unroll
        for (int j = 0; j < 4; j++) {
            const int col = wc * 64 + j * 16;
            wmma::fragment<wmma::matrix_b, 16, 16, 16, __half, wmma::row_major> bh;
            wmma::load_matrix_sync(bh, sWh + k0 * PAD + col, PAD);
            #pragma unroll
            for (int r = 0; r < 2; r++)
                wmma::mma_sync(acc[r][j], ah[r], bh, acc[r][j]);
        }
    }

    __syncthreads();   // W and A reads complete; reuse smem as fp32 C
    #pragma unroll
    for (int r = 0; r < 2; r++)
        #pragma unroll
        for (int j = 0; j < 4; j++)
            wmma::store_matrix_sync(
                sC + (wr * 32 + r * 16) * HD + wc * 64 + j * 16,
                acc[r][j], HD, wmma::mem_row_major);
    __syncthreads();

    const int tx = tid & 31;
    const int ty = tid >> 5;
    #pragma unroll
    for (int i = 0; i < 16; i++) {
        int rl = ty * 16 + i;
        int r  = row0 + rl;
        if (r < N) {
            float4 v = *reinterpret_cast<float4*>(sC + rl * HD + tx * 4);
            __half2 lo = __float22half2_rn(make_float2(v.x, v.y));
            __half2 hi = __float22half2_rn(make_float2(v.z, v.w));
            uint2 p;
            p.x = *reinterpret_cast<unsigned*>(&lo);
            p.y = *reinterpret_cast<unsigned*>(&hi);
            reinterpret_cast<uint2*>(g_X0q)[(size_t)r * 32 + tx] = p;
            if (r >= g)
                out4[(size_t)(N + r - g) * 32 + tx] = v;
        }
    }
}

// ---------------------------------------------------------------------------
__global__ void hist_kernel(const int* __restrict__ esrc, int E) {
    for (int e = blockIdx.x * blockDim.x + threadIdx.x; e < E;
         e += gridDim.x * blockDim.x)
        atomicAdd(&g_cnt[esrc[e]], 1);
}

// ---------------------------------------------------------------------------
// Fused exclusive scan (decoupled lookback), identical to R12.
// ---------------------------------------------------------------------------
__global__ __launch_bounds__(256) void scan_kernel(int N, int E) {
    __shared__ int ssum[256];
    __shared__ int s_bpre;
    const int t   = threadIdx.x;
    const int bid = blockIdx.x;
    const int base = bid * SCAN_BLK + t * 4;

    int c0 = 0, c1 = 0, c2 = 0, c3 = 0;
    if (base + 0 < N) { c0 = g_cnt[base + 0]; g_cnt[base + 0] = 0; }
    if (base + 1 < N) { c1 = g_cnt[base + 1]; g_cnt[base + 1] = 0; }
    if (base + 2 < N) { c2 = g_cnt[base + 2]; g_cnt[base + 2] = 0; }
    if (base + 3 < N) { c3 = g_cnt[base + 3]; g_cnt[base + 3] = 0; }
    int tot = c0 + c1 + c2 + c3;

    ssum[t] = tot;
    __syncthreads();
    #pragma unroll
    for (int off = 1; off < 256; off <<= 1) {
        int v = (t >= off) ? ssum[t - off] : 0;
        __syncthreads();
        ssum[t] += v;
        __syncthreads();
    }
    int ex = ssum[t] - tot;

    if (t == 0)
        atomicExch(&g_agg[bid], (1ULL << 32) | (unsigned)ssum[255]);

    if (t < 32) {
        int prefix = 0;
        for (int ws = 0; ws < bid; ws += 32) {
            int j = ws + t;
            unsigned val = 0;
            if (j < bid) {
                unsigned long long v;
                do { v = atomicAdd(&g_agg[j], 0ULL); } while (!(v >> 32));
                val = (unsigned)v;
            }
            #pragma unroll
            for (int o = 16; o; o >>= 1)
                val += __shfl_down_sync(0xffffffffu, val, o);
            if (t == 0) prefix += (int)val;
        }
        if (t == 0) s_bpre = prefix;
    }
    __syncthreads();

    const int boff = s_bpre;
    if (base + 0 < N) { int v = ex + boff;                g_off[base + 0] = v; g_cur[base + 0] = v; }
    if (base + 1 < N) { int v = ex + c0 + boff;           g_off[base + 1] = v; g_cur[base + 1] = v; }
    if (base + 2 < N) { int v = ex + c0 + c1 + boff;      g_off[base + 2] = v; g_cur[base + 2] = v; }
    if (base + 3 < N) { int v = ex + c0 + c1 + c2 + boff; g_off[base + 3] = v; g_cur[base + 3] = v; }
    if (bid == 0 && t == 0) g_off[N] = E;
}

// ---------------------------------------------------------------------------
__global__ void scatter_kernel(const int* __restrict__ esrc,
                               const int* __restrict__ edst,
                               const float* __restrict__ ew, int E) {
    if (blockIdx.x == 0 && threadIdx.x < 256)
        g_agg[threadIdx.x] = 0ULL;
    for (int e = blockIdx.x * blockDim.x + threadIdx.x; e < E;
         e += gridDim.x * blockDim.x) {
        int s = esrc[e];
        int p = atomicAdd(&g_cur[s], 1);
        g_sdw[p] = make_int2(edst[e], __float_as_int(ew[e]));
    }
}

// ---------------------------------------------------------------------------
// Gather (identical to R12): 2 nodes/warp, half-warp per node, uint4 loads.
// ---------------------------------------------------------------------------
__global__ __launch_bounds__(256) void gather_kernel(
    const float4* __restrict__ b4,
    float4* __restrict__ out4,
    int N)
{
    const int lane = threadIdx.x & 31;
    const int sub  = lane >> 4;
    const int hl   = lane & 15;
    const int wnum = (blockIdx.x * blockDim.x + threadIdx.x) >> 5;
    const int node = wnum * 2 + sub;
    const bool active = node < N;
    const int  vnode  = active ? node : N - 1;

    const int start = g_off[vnode];
    const int cnt   = active ? (g_off[vnode + 1] - start) : 0;

    const int ocnt   = __shfl_xor_sync(0xffffffffu, cnt, 16);
    const int maxcnt = max(cnt, ocnt);

    float acc[8];
    #pragma unroll
    for (int i = 0; i < 8; i++) acc[i] = 0.f;

    for (int it = 0; it < maxcnt; it += 16) {
        const int m  = min(16, cnt - it);
        const int mu = min(16, maxcnt - it);
        int   dv = 0;
        float wv = 0.f;
        if (hl < m) {
            int2 p = g_sdw[start + it + hl];
            dv = p.x;
            wv = __int_as_float(p.y);
        }
        for (int k = 0; k < mu; k++) {
            int   d = __shfl_sync(0xffffffffu, dv, sub * 16 + k);
            float w = __shfl_sync(0xffffffffu, wv, sub * 16 + k);
            if (k < m) {
                uint4 u = g_X0q[(size_t)d * 16 + hl];
                float2 f0 = __half22float2(*reinterpret_cast<__half2*>(&u.x));
                float2 f1 = __half22float2(*reinterpret_cast<__half2*>(&u.y));
                float2 f2 = __half22float2(*reinterpret_cast<__half2*>(&u.z));
                float2 f3 = __half22float2(*reinterpret_cast<__half2*>(&u.w));
                acc[0] += w * f0.x;  acc[1] += w * f0.y;
                acc[2] += w * f1.x;  acc[3] += w * f1.y;
                acc[4] += w * f2.x;  acc[5] += w * f2.y;
                acc[6] += w * f3.x;  acc[7] += w * f3.y;
            }
        }
    }

    if (active) {
        float4 b0 = __ldg(b4 + hl * 2 + 0);
        float4 b1 = __ldg(b4 + hl * 2 + 1);
        float4 v0 = make_float4(fmaxf(acc[0] + b0.x, 0.f),
                                fmaxf(acc[1] + b0.y, 0.f),
                                fmaxf(acc[2] + b0.z, 0.f),
                                fmaxf(acc[3] + b0.w, 0.f));
        float4 v1 = make_float4(fmaxf(acc[4] + b1.x, 0.f),
                                fmaxf(acc[5] + b1.y, 0.f),
                                fmaxf(acc[6] + b1.z, 0.f),
                                fmaxf(acc[7] + b1.w, 0.f));
        out4[(size_t)node * 32 + hl * 2 + 0] = v0;
        out4[(size_t)node * 32 + hl * 2 + 1] = v1;
    }
}

// ---------------------------------------------------------------------------
extern "C" void kernel_launch(void* const* d_in, const int* in_sizes, int n_in,
                              void* d_out, int out_size)
{
    const float* notes = (const float*)d_in[0];
    const float* w     = (const float*)d_in[1];
    const float* b     = (const float*)d_in[2];
    const int*   esrc  = (const int*)  d_in[3];
    const int*   edst  = (const int*)  d_in[4];
    const float* ew    = (const float*)d_in[5];

    const int H = in_sizes[2];
    const int D = in_sizes[1] / H;
    const int N = in_sizes[0] / D;
    const int E = in_sizes[3];
    const int g = 2 * N - out_size / H;

    float4* out4 = (float4*)d_out;
    const int NB = (N + SCAN_BLK - 1) / SCAN_BLK;

    cudaFuncSetAttribute(gemm_kernel,
                         cudaFuncAttributeMaxDynamicSharedMemorySize,
                         SMEM_BYTES);

    hist_kernel<<<592, 256>>>(esrc, E);
    scan_kernel<<<NB, 256>>>(N, E);
    scatter_kernel<<<592, 256>>>(esrc, edst, ew, E);

    gemm_kernel<<<(N + BM - 1) / BM, 256, SMEM_BYTES>>>(
        (const float4*)notes, (const float4*)w, out4, N, g);

    gather_kernel<<<(N + 15) / 16, 256>>>(
        (const float4*)b, out4, N);
}